// round 6
// baseline (speedup 1.0000x reference)
#include <cuda_runtime.h>
#include <math.h>

// ---------------- problem constants (fixed by the reference) ----------------
#define BB 2
#define LL 2048
#define HH 768
#define EE 1536
#define NNS 16           // state dim N
#define RRK 4            // dt rank R
#define CC 3
#define NLAYER 8
#define TT (BB*LL)       // 4096 rows
#define NCH 16           // scan chunks per sequence
#define TCH (LL/NCH)     // 128 steps per chunk

// ---------------- scratch (device globals: no runtime allocation) ----------
__device__ float g_hs  [TT*HH];
__device__ float g_x   [TT*HH];
__device__ float g_proj[TT*2*EE];
__device__ float g_u   [TT*EE];
__device__ float g_dbc [TT*36];
__device__ float g_dt  [TT*EE];
__device__ float g_y   [TT*EE];
__device__ float g_cP   [BB*NCH*NNS*EE];
__device__ float g_cH   [BB*NCH*NNS*EE];
__device__ float g_hinit[BB*NCH*NNS*EE];
__device__ float g_t1  [TT*HH];
__device__ float g_t2  [TT*HH];
__device__ float g_accb[TT*HH];

// ---------------- helpers ----------------
__device__ __forceinline__ float silu_f(float v)    { return v / (1.0f + expf(-v)); }
__device__ __forceinline__ float sigmoid_f(float v) { return 1.0f / (1.0f + expf(-v)); }
__device__ __forceinline__ float softplus_f(float v){ return (v > 20.0f) ? v : log1pf(expf(v)); }

// ---------------- embedding ----------------
__global__ void embed_kernel(const int* __restrict__ ids,
                             const float* __restrict__ tok,
                             const float* __restrict__ pos,
                             float* __restrict__ hs)
{
    int g = blockIdx.x * blockDim.x + threadIdx.x;   // TT*HH
    if (g >= TT*HH) return;
    int h   = g % HH;
    int row = g / HH;
    int t   = row % LL;
    hs[g] = tok[(size_t)ids[row]*HH + h] + pos[(size_t)t*HH + h];
}

// ---------------- layernorm (one block per row of 768) ----------------
__global__ __launch_bounds__(256) void ln_kernel(const float* __restrict__ in,
                                                 const float* __restrict__ w,
                                                 const float* __restrict__ b,
                                                 float* __restrict__ out)
{
    __shared__ float red[256];
    int row = blockIdx.x, tid = threadIdx.x;
    const float* x = in + (size_t)row*HH;
    float v0 = x[tid], v1 = x[tid+256], v2 = x[tid+512];
    red[tid] = v0 + v1 + v2;
    __syncthreads();
    #pragma unroll
    for (int s = 128; s > 0; s >>= 1) { if (tid < s) red[tid] += red[tid+s]; __syncthreads(); }
    float mean = red[0] * (1.0f/768.0f);
    __syncthreads();
    float d0 = v0-mean, d1 = v1-mean, d2 = v2-mean;
    red[tid] = d0*d0 + d1*d1 + d2*d2;
    __syncthreads();
    #pragma unroll
    for (int s = 128; s > 0; s >>= 1) { if (tid < s) red[tid] += red[tid+s]; __syncthreads(); }
    float inv = rsqrtf(red[0] * (1.0f/768.0f) + 1e-5f);
    float* o = out + (size_t)row*HH;
    o[tid]     = d0*inv*w[tid]     + b[tid];
    o[tid+256] = d1*inv*w[tid+256] + b[tid+256];
    o[tid+512] = d2*inv*w[tid+512] + b[tid+512];
}

// ---------------- generic fp32 GEMM: C = act(A*W + bias) [+res] [accum] ----
// A: MxK row-major, W: KxN row-major. M%128==0, K%16==0, N%64==0.
__global__ __launch_bounds__(256) void gemm_kernel(
    const float* __restrict__ A, const float* __restrict__ W,
    const float* __restrict__ bias, const float* __restrict__ Rres,
    float* __restrict__ Cout, int M, int Kd, int Nd, int act, int accum)
{
    __shared__ __align__(16) float As[16][132];
    __shared__ __align__(16) float Bs[16][64];
    const int tid = threadIdx.x;
    const int bm  = blockIdx.y * 128;
    const int bn  = blockIdx.x * 64;
    const int m0  = (tid >> 4) * 8;
    const int n0  = (tid & 15) * 4;
    const int arow = tid >> 2;
    const int acol = (tid & 3) * 4;
    const int brow = tid >> 4;
    const int bcol = (tid & 15) * 4;

    float acc[8][4];
    #pragma unroll
    for (int i = 0; i < 8; i++)
        #pragma unroll
        for (int j = 0; j < 4; j++) acc[i][j] = 0.0f;

    for (int k0 = 0; k0 < Kd; k0 += 16) {
        #pragma unroll
        for (int r = 0; r < 2; r++) {
            int m = arow + r*64;
            const float4 v = *(const float4*)(A + (size_t)(bm + m)*Kd + k0 + acol);
            As[acol+0][m] = v.x; As[acol+1][m] = v.y;
            As[acol+2][m] = v.z; As[acol+3][m] = v.w;
        }
        {
            const float4 v = *(const float4*)(W + (size_t)(k0 + brow)*Nd + bn + bcol);
            *(float4*)(&Bs[brow][bcol]) = v;
        }
        __syncthreads();
        #pragma unroll
        for (int kk = 0; kk < 16; kk++) {
            float4 a0 = *(const float4*)(&As[kk][m0]);
            float4 a1 = *(const float4*)(&As[kk][m0+4]);
            float4 b0 = *(const float4*)(&Bs[kk][n0]);
            float af[8] = {a0.x,a0.y,a0.z,a0.w,a1.x,a1.y,a1.z,a1.w};
            float bf[4] = {b0.x,b0.y,b0.z,b0.w};
            #pragma unroll
            for (int i = 0; i < 8; i++)
                #pragma unroll
                for (int j = 0; j < 4; j++)
                    acc[i][j] = fmaf(af[i], bf[j], acc[i][j]);
        }
        __syncthreads();
    }

    #pragma unroll
    for (int i = 0; i < 8; i++) {
        int m = bm + m0 + i;
        #pragma unroll
        for (int j = 0; j < 4; j++) {
            int n = bn + n0 + j;
            float v = acc[i][j] + bias[n];
            if (act) v = silu_f(v);
            size_t idx = (size_t)m * Nd + n;
            if (Rres)  v += Rres[idx];
            if (accum) Cout[idx] += v;
            else       Cout[idx]  = v;
        }
    }
}

// ---------------- causal depthwise conv (K=4) + SiLU, reads xm from proj ----
__global__ void conv_silu_kernel(const float* __restrict__ proj,
                                 const float* __restrict__ cw,
                                 const float* __restrict__ cb,
                                 float* __restrict__ u)
{
    int g = blockIdx.x * blockDim.x + threadIdx.x;   // TT*EE
    if (g >= TT*EE) return;
    int e   = g % EE;
    int row = g / EE;
    int t   = row % LL;
    int b   = row / LL;
    float acc = cb[e];
    #pragma unroll
    for (int j = 0; j < 4; j++) {
        int tt = t - 3 + j;
        if (tt >= 0)
            acc = fmaf(proj[(size_t)(b*LL + tt)*(2*EE) + e], cw[e*4 + j], acc);
    }
    u[g] = silu_f(acc);
}

// ---------------- dbc = u @ xproj_w  (4096 x 1536 x 36 skinny GEMM) --------
__global__ __launch_bounds__(288) void dbc_kernel(const float* __restrict__ u,
                                                  const float* __restrict__ w,
                                                  float* __restrict__ dbc)
{
    __shared__ float su[EE];
    __shared__ float part[8][36];
    int row = blockIdx.x;
    for (int i = threadIdx.x; i < EE; i += 288) su[i] = u[(size_t)row*EE + i];
    __syncthreads();
    int j = threadIdx.x % 36, s = threadIdx.x / 36;   // 36 cols x 8 k-slices
    float acc = 0.0f;
    int k0 = s * (EE/8);
    for (int k = k0; k < k0 + EE/8; k++)
        acc = fmaf(su[k], w[k*36 + j], acc);
    part[s][j] = acc;
    __syncthreads();
    if (threadIdx.x < 36) {
        float t = 0.0f;
        #pragma unroll
        for (int ss = 0; ss < 8; ss++) t += part[ss][threadIdx.x];
        dbc[row*36 + threadIdx.x] = t;
    }
}

// ---------------- dt = softplus(dbc[:, :4] @ dt_w + dt_b) ------------------
__global__ void dt_kernel(const float* __restrict__ dbc,
                          const float* __restrict__ dtw,
                          const float* __restrict__ dtb,
                          float* __restrict__ dt)
{
    int g = blockIdx.x * blockDim.x + threadIdx.x;   // TT*EE
    if (g >= TT*EE) return;
    int e = g % EE, row = g / EE;
    float v = dtb[e];
    #pragma unroll
    for (int r = 0; r < 4; r++)
        v = fmaf(dbc[row*36 + r], dtw[r*EE + e], v);
    dt[g] = softplus_f(v);
}

// ---------------- scan pass A: per-chunk (prod dA, h'|h0=0) ----------------
// thread map: e fastest -> coalesced dt/u, broadcast B. total B*NCH*NNS*EE.
__global__ void scan_chunk_kernel(const float* __restrict__ dtp,
                                  const float* __restrict__ up,
                                  const float* __restrict__ dbc,
                                  const float* __restrict__ A_log,
                                  float* __restrict__ cP, float* __restrict__ cH)
{
    int g = blockIdx.x * blockDim.x + threadIdx.x;
    int e = g % EE;
    int n = (g / EE) % NNS;
    int c = (g / (EE*NNS)) % NCH;
    int b =  g / (EE*NNS*NCH);
    float Aen = -expf(A_log[e*NNS + n]);
    float p = 1.0f, h = 0.0f;
    int rbase = b*LL + c*TCH;
    for (int t = 0; t < TCH; t++) {
        int row   = rbase + t;
        float dtv = dtp[(size_t)row*EE + e];
        float uv  = up [(size_t)row*EE + e];
        float bv  = dbc[row*36 + 4 + n];
        float dA  = expf(dtv * Aen);
        p *= dA;
        h = fmaf(h, dA, dtv * uv * bv);
    }
    size_t idx = ((size_t)((b*NCH + c)*NNS + n))*EE + e;
    cP[idx] = p; cH[idx] = h;
}

// ---------------- scan pass B: sequential carry across 16 chunks -----------
__global__ void scan_carry_kernel(const float* __restrict__ cP,
                                  const float* __restrict__ cH,
                                  float* __restrict__ hinit)
{
    int g = blockIdx.x * blockDim.x + threadIdx.x;   // BB*NNS*EE
    if (g >= BB*NNS*EE) return;
    int e = g % EE;
    int n = (g / EE) % NNS;
    int b =  g / (EE*NNS);
    float h = 0.0f;
    for (int c = 0; c < NCH; c++) {
        size_t idx = ((size_t)((b*NCH + c)*NNS + n))*EE + e;
        hinit[idx] = h;
        h = fmaf(cP[idx], h, cH[idx]);
    }
}

// ---------------- scan pass C: rescan with carry, reduce over n, gate ------
// thread map: n fastest (16 lanes per e) -> shuffle-reduce within warp halves.
__global__ void scan_y_kernel(const float* __restrict__ dtp,
                              const float* __restrict__ up,
                              const float* __restrict__ dbc,
                              const float* __restrict__ hinit,
                              const float* __restrict__ A_log,
                              const float* __restrict__ Dv,
                              const float* __restrict__ proj,
                              float* __restrict__ y)
{
    int g = blockIdx.x * blockDim.x + threadIdx.x;
    int n = g % NNS;
    int e = (g / NNS) % EE;
    int c = (g / (NNS*EE)) % NCH;
    int b =  g / (NNS*EE*NCH);
    float Aen  = -expf(A_log[e*NNS + n]);
    float h    = hinit[((size_t)((b*NCH + c)*NNS + n))*EE + e];
    float Dval = Dv[e];
    int t0 = c*TCH;
    for (int t = t0; t < t0 + TCH; t++) {
        int row   = b*LL + t;
        float dtv = dtp[(size_t)row*EE + e];
        float uv  = up [(size_t)row*EE + e];
        float bv  = dbc[row*36 + 4  + n];
        float cv  = dbc[row*36 + 20 + n];
        h = fmaf(h, expf(dtv * Aen), dtv * uv * bv);
        float part = h * cv;
        part += __shfl_xor_sync(0xffffffffu, part, 8);
        part += __shfl_xor_sync(0xffffffffu, part, 4);
        part += __shfl_xor_sync(0xffffffffu, part, 2);
        part += __shfl_xor_sync(0xffffffffu, part, 1);
        if (n == 0) {
            float gate = proj[(size_t)row*(2*EE) + EE + e];
            y[(size_t)row*EE + e] = (part + uv*Dval) * sigmoid_f(gate);
        }
    }
}

// ---------------- small elementwise ----------------
__global__ void zero_kernel(float* __restrict__ p, int n)
{
    int g = blockIdx.x * blockDim.x + threadIdx.x;
    if (g < n) p[g] = 0.0f;
}
__global__ void frac_add_kernel(float* __restrict__ hs, const float* __restrict__ acc, int n)
{
    int g = blockIdx.x * blockDim.x + threadIdx.x;
    if (g < n) hs[g] = fmaf(acc[g], 0.5f/3.0f, hs[g]);
}

// ---------------- host orchestration ----------------
extern "C" void kernel_launch(void* const* d_in, const int* in_sizes, int n_in,
                              void* d_out, int out_size)
{
    const int*   input_ids = (const int*)  d_in[0];
    const float* tok_emb   = (const float*)d_in[1];
    const float* pos_emb   = (const float*)d_in[2];
    const float* ln_w      = (const float*)d_in[3];
    const float* ln_b      = (const float*)d_in[4];
    const float* in_w      = (const float*)d_in[5];
    const float* in_b      = (const float*)d_in[6];
    const float* conv_w    = (const float*)d_in[7];
    const float* conv_b    = (const float*)d_in[8];
    const float* xproj_w   = (const float*)d_in[9];
    const float* dt_w      = (const float*)d_in[10];
    const float* dt_b      = (const float*)d_in[11];
    const float* A_log     = (const float*)d_in[12];
    const float* Dvec      = (const float*)d_in[13];
    const float* out_w     = (const float*)d_in[14];
    const float* out_b     = (const float*)d_in[15];
    const float* frac_w    = (const float*)d_in[16];
    const float* frac_b    = (const float*)d_in[17];
    const float* fln_w     = (const float*)d_in[18];
    const float* fln_b     = (const float*)d_in[19];
    float* outp = (float*)d_out;

    float *hs, *x, *proj, *u, *dbc, *dt, *y, *cP, *cH, *hinit, *t1, *t2, *accb;
    cudaGetSymbolAddress((void**)&hs,    g_hs);
    cudaGetSymbolAddress((void**)&x,     g_x);
    cudaGetSymbolAddress((void**)&proj,  g_proj);
    cudaGetSymbolAddress((void**)&u,     g_u);
    cudaGetSymbolAddress((void**)&dbc,   g_dbc);
    cudaGetSymbolAddress((void**)&dt,    g_dt);
    cudaGetSymbolAddress((void**)&y,     g_y);
    cudaGetSymbolAddress((void**)&cP,    g_cP);
    cudaGetSymbolAddress((void**)&cH,    g_cH);
    cudaGetSymbolAddress((void**)&hinit, g_hinit);
    cudaGetSymbolAddress((void**)&t1,    g_t1);
    cudaGetSymbolAddress((void**)&t2,    g_t2);
    cudaGetSymbolAddress((void**)&accb,  g_accb);

    const int EW = TT*HH;          // elementwise over hidden
    const int EWE = TT*EE;
    const int SCAN_T = BB*NCH*NNS*EE;    // 786432

    embed_kernel<<<(EW + 255)/256, 256>>>(input_ids, tok_emb, pos_emb, hs);

    for (int l = 0; l < NLAYER; l++) {
        // x = LN(hs)
        ln_kernel<<<TT, 256>>>(hs, ln_w + l*HH, ln_b + l*HH, x);
        // proj = x @ in_w + in_b      (4096 x 768 x 3072)
        gemm_kernel<<<dim3(2*EE/64, TT/128), 256>>>(
            x, in_w + (size_t)l*HH*2*EE, in_b + l*2*EE, nullptr, proj,
            TT, HH, 2*EE, 0, 0);
        // u = silu(causal_dwconv(proj[:, :E]))
        conv_silu_kernel<<<(EWE + 255)/256, 256>>>(proj, conv_w + l*EE*4, conv_b + l*EE, u);
        // dbc = u @ xproj_w
        dbc_kernel<<<TT, 288>>>(u, xproj_w + (size_t)l*EE*36, dbc);
        // dt = softplus(dbc[:, :4] @ dt_w + dt_b)
        dt_kernel<<<(EWE + 255)/256, 256>>>(dbc, dt_w + l*RRK*EE, dt_b + l*EE, dt);
        // chunked selective scan
        scan_chunk_kernel<<<SCAN_T/256, 256>>>(dt, u, dbc, A_log + (size_t)l*EE*NNS, cP, cH);
        scan_carry_kernel<<<(BB*NNS*EE + 255)/256, 256>>>(cP, cH, hinit);
        scan_y_kernel<<<SCAN_T/256, 256>>>(dt, u, dbc, hinit,
            A_log + (size_t)l*EE*NNS, Dvec + l*EE, proj, y);
        // hs = y @ out_w + out_b + hs  (residual fused)
        gemm_kernel<<<dim3(HH/64, TT/128), 256>>>(
            y, out_w + (size_t)l*EE*HH, out_b + l*HH, hs, hs,
            TT, EE, HH, 0, 0);
        // fractal refinement: acc = sum_i silu^3(hs; W_i); hs += acc/6
        zero_kernel<<<(EW + 255)/256, 256>>>(accb, EW);
        for (int i = 0; i < CC; i++) {
            const float* Wp = frac_w + (size_t)(l*CC + i)*HH*HH;
            const float* bp = frac_b + (size_t)(l*CC + i)*HH;
            gemm_kernel<<<dim3(HH/64, TT/128), 256>>>(hs, Wp, bp, nullptr, t1, TT, HH, HH, 1, 0);
            gemm_kernel<<<dim3(HH/64, TT/128), 256>>>(t1, Wp, bp, nullptr, t2, TT, HH, HH, 1, 0);
            gemm_kernel<<<dim3(HH/64, TT/128), 256>>>(t2, Wp, bp, nullptr, accb, TT, HH, HH, 1, 1);
        }
        frac_add_kernel<<<(EW + 255)/256, 256>>>(hs, accb, EW);
    }

    // final layernorm -> output (float32)
    ln_kernel<<<TT, 256>>>(hs, fln_w, fln_b, outp);
    (void)in_sizes; (void)n_in; (void)out_size;
}